// round 11
// baseline (speedup 1.0000x reference)
#include <cuda_runtime.h>
#include <cuda_bf16.h>
#include <cstdint>
#include <math.h>

#define NN_MAX 100000
#define NE_MAX 3200000
#define HIDC   256
#define INFEAT 128

// ---------------- scratch (static __device__ globals; no allocation) ----------
__device__ float g_h  [(size_t)NN_MAX * HIDC];
__device__ float g_f  [(size_t)NN_MAX * HIDC];
__device__ __nv_bfloat16 g_hb [(size_t)NN_MAX * HIDC], g_hl [(size_t)NN_MAX * HIDC];
__device__ __nv_bfloat16 g_fhb[(size_t)NN_MAX * HIDC], g_fhl[(size_t)NN_MAX * HIDC];
__device__ __nv_bfloat16 g_mb [(size_t)NN_MAX * HIDC], g_ml [(size_t)NN_MAX * HIDC];
__device__ __nv_bfloat16 g_xb [(size_t)NN_MAX * INFEAT], g_xl [(size_t)NN_MAX * INFEAT];
// fragment-ordered weights: [K/16][N/8][32 lanes][2 regs] as uint2 per lane
__device__ uint2 g_wih[4096],  g_wil[4096];
__device__ uint2 g_wfh[16384], g_wfl[16384];
__device__ uint2 g_ufh[16384], g_ufl[16384];
__device__ uint2 g_whh[16384], g_whl[16384];
__device__ uint2 g_uhh[16384], g_uhl[16384];
// CSR (grouped by destination)
__device__ int g_icnt[NN_MAX];
__device__ int g_off [NN_MAX + 1];
__device__ int g_pos [NN_MAX];
__device__ int g_csrc[NE_MAX];
__device__ float g_sum[HIDC];

__device__ __forceinline__ uint32_t smem_to_u32(const void* p) {
    uint32_t a;
    asm("{ .reg .u64 t; cvta.to.shared.u64 t, %1; cvt.u32.u64 %0, t; }" : "=r"(a) : "l"(p));
    return a;
}
__device__ __forceinline__ void cp_async16(uint32_t dst, const void* src, int src_bytes) {
    asm volatile("cp.async.cg.shared.global [%0], [%1], 16, %2;"
                 :: "r"(dst), "l"(src), "r"(src_bytes));
}
__device__ __forceinline__ void cp_commit() { asm volatile("cp.async.commit_group;"); }
__device__ __forceinline__ void cp_wait0() { asm volatile("cp.async.wait_group 0;"); }

__device__ __forceinline__ void split_pair(float a, float b,
                                           __nv_bfloat162& hi, __nv_bfloat162& lo) {
    __nv_bfloat16 h0 = __float2bfloat16_rn(a);
    __nv_bfloat16 h1 = __float2bfloat16_rn(b);
    hi = __nv_bfloat162(h0, h1);
    lo = __nv_bfloat162(__float2bfloat16_rn(a - __bfloat162float(h0)),
                        __float2bfloat16_rn(b - __bfloat162float(h1)));
}

// ---------------- CSR build ----------------
__global__ void count_kernel(const int* __restrict__ dst, int nE) {
    int i = blockIdx.x * blockDim.x + threadIdx.x;
    if (i < nE) atomicAdd(&g_icnt[dst[i]], 1);
}

__global__ void scan_kernel(int nN) {
    __shared__ int part[1024];
    int t = threadIdx.x;
    int chunk = (nN + 1023) / 1024;
    int b = t * chunk;
    int e = min(b + chunk, nN);
    int s = 0;
    for (int i = b; i < e; ++i) s += g_icnt[i];
    part[t] = s;
    __syncthreads();
    for (int d = 1; d < 1024; d <<= 1) {
        int v = (t >= d) ? part[t - d] : 0;
        __syncthreads();
        part[t] += v;
        __syncthreads();
    }
    int run = part[t] - s;
    for (int i = b; i < e; ++i) {
        g_off[i] = run;
        g_pos[i] = run;
        run += g_icnt[i];
    }
    if (t == 1023) g_off[nN] = part[1023];
}

__global__ void fill_kernel(const int* __restrict__ src,
                            const int* __restrict__ dst, int nE) {
    int i = blockIdx.x * blockDim.x + threadIdx.x;
    if (i < nE) {
        int p = atomicAdd(&g_pos[dst[i]], 1);
        g_csrc[p] = src[i];
    }
}

// ---------------- pull-mode aggregation: one warp per destination node -------
__global__ __launch_bounds__(256)
void gather_kernel(int nN) {
    int w = (blockIdx.x * blockDim.x + threadIdx.x) >> 5;
    int lane = threadIdx.x & 31;
    if (w >= nN) return;
    int beg = g_off[w], end = g_off[w + 1];
    float acc[8] = {0.f, 0.f, 0.f, 0.f, 0.f, 0.f, 0.f, 0.f};
    int e = beg;
    for (; e + 3 < end; e += 4) {
        int s0 = g_csrc[e], s1 = g_csrc[e + 1], s2 = g_csrc[e + 2], s3 = g_csrc[e + 3];
        const float4* r0 = reinterpret_cast<const float4*>(g_h + (size_t)s0 * HIDC) + lane * 2;
        const float4* r1 = reinterpret_cast<const float4*>(g_h + (size_t)s1 * HIDC) + lane * 2;
        const float4* r2 = reinterpret_cast<const float4*>(g_h + (size_t)s2 * HIDC) + lane * 2;
        const float4* r3 = reinterpret_cast<const float4*>(g_h + (size_t)s3 * HIDC) + lane * 2;
        float4 a0 = r0[0], a1 = r0[1], b0 = r1[0], b1 = r1[1];
        float4 c0 = r2[0], c1 = r2[1], d0 = r3[0], d1 = r3[1];
        acc[0] += (a0.x + b0.x) + (c0.x + d0.x);
        acc[1] += (a0.y + b0.y) + (c0.y + d0.y);
        acc[2] += (a0.z + b0.z) + (c0.z + d0.z);
        acc[3] += (a0.w + b0.w) + (c0.w + d0.w);
        acc[4] += (a1.x + b1.x) + (c1.x + d1.x);
        acc[5] += (a1.y + b1.y) + (c1.y + d1.y);
        acc[6] += (a1.z + b1.z) + (c1.z + d1.z);
        acc[7] += (a1.w + b1.w) + (c1.w + d1.w);
    }
    for (; e < end; ++e) {
        int s0 = g_csrc[e];
        const float4* r0 = reinterpret_cast<const float4*>(g_h + (size_t)s0 * HIDC) + lane * 2;
        float4 a0 = r0[0], a1 = r0[1];
        acc[0] += a0.x; acc[1] += a0.y; acc[2] += a0.z; acc[3] += a0.w;
        acc[4] += a1.x; acc[5] += a1.y; acc[6] += a1.z; acc[7] += a1.w;
    }
    float inv = 1.f / fmaxf((float)(end - beg), 1.f);
    __nv_bfloat162 hi[4], lo[4];
    split_pair(acc[0] * inv, acc[1] * inv, hi[0], lo[0]);
    split_pair(acc[2] * inv, acc[3] * inv, hi[1], lo[1]);
    split_pair(acc[4] * inv, acc[5] * inv, hi[2], lo[2]);
    split_pair(acc[6] * inv, acc[7] * inv, hi[3], lo[3]);
    size_t o = (size_t)w * HIDC + lane * 8;
    *reinterpret_cast<uint4*>(g_mb + o) = *reinterpret_cast<const uint4*>(hi);
    *reinterpret_cast<uint4*>(g_ml + o) = *reinterpret_cast<const uint4*>(lo);
}

// ---------------- consolidated prep: 5 weight-frag sections + x split --------
__device__ void wfrag_one(const float* W, uint2* hi, uint2* lo, int N, int K, int i) {
    int lane = i & 31;
    int rest = i >> 5;
    int n8 = rest % (N / 8);
    int k16 = rest / (N / 8);
    int n = n8 * 8 + (lane >> 2);
    uint32_t rh[2], rl[2];
#pragma unroll
    for (int reg = 0; reg < 2; ++reg) {
        int k = k16 * 16 + reg * 8 + (lane & 3) * 2;
        float w0 = W[(size_t)n * K + k];
        float w1 = W[(size_t)n * K + k + 1];
        __nv_bfloat16 h0 = __float2bfloat16_rn(w0);
        __nv_bfloat16 h1 = __float2bfloat16_rn(w1);
        rh[reg] = ((uint32_t)__bfloat16_as_ushort(h1) << 16) | __bfloat16_as_ushort(h0);
        rl[reg] = ((uint32_t)__bfloat16_as_ushort(__float2bfloat16_rn(w1 - __bfloat162float(h1))) << 16)
                | __bfloat16_as_ushort(__float2bfloat16_rn(w0 - __bfloat162float(h0)));
    }
    hi[i] = make_uint2(rh[0], rh[1]);
    lo[i] = make_uint2(rl[0], rl[1]);
}

__global__ void prep_kernel(const float* __restrict__ x,
                            const float* __restrict__ Win, const float* __restrict__ Wf,
                            const float* __restrict__ Uf, const float* __restrict__ Wh,
                            const float* __restrict__ Uh, int nx) {
    int i = blockIdx.x * blockDim.x + threadIdx.x;
    if (i < 4096) { wfrag_one(Win, g_wih, g_wil, 128, 128, i); return; }
    i -= 4096;
    if (i < 16384) { wfrag_one(Wf, g_wfh, g_wfl, 256, 256, i); return; }
    i -= 16384;
    if (i < 16384) { wfrag_one(Uf, g_ufh, g_ufl, 256, 256, i); return; }
    i -= 16384;
    if (i < 16384) { wfrag_one(Wh, g_whh, g_whl, 256, 256, i); return; }
    i -= 16384;
    if (i < 16384) { wfrag_one(Uh, g_uhh, g_uhl, 256, 256, i); return; }
    i -= 16384;
    int j = i * 2;
    if (j < nx) {
        __nv_bfloat162 hi, lo;
        split_pair(x[j], x[j + 1], hi, lo);
        *reinterpret_cast<__nv_bfloat162*>(g_xb + j) = hi;
        *reinterpret_cast<__nv_bfloat162*>(g_xl + j) = lo;
    }
}

// ---------------- HMMA dual-GEMM, cp.async double-buffered A staging ----------
// C = sum_pass [ Ah*(Wh+Wl) + Al*Wh ]
__device__ __forceinline__ void mma16816(float c[4], const uint32_t a[4], uint2 b) {
    asm volatile("mma.sync.aligned.m16n8k16.row.col.f32.bf16.bf16.f32 "
                 "{%0,%1,%2,%3}, {%4,%5,%6,%7}, {%8,%9}, {%0,%1,%2,%3};"
                 : "+f"(c[0]), "+f"(c[1]), "+f"(c[2]), "+f"(c[3])
                 : "r"(a[0]), "r"(a[1]), "r"(a[2]), "r"(a[3]), "r"(b.x), "r"(b.y));
}

__global__ __launch_bounds__(256)
void gemm_mma(const __nv_bfloat16* __restrict__ A0h, const __nv_bfloat16* __restrict__ A0l,
              const uint2* __restrict__ W0h, const uint2* __restrict__ W0l, int K0,
              const __nv_bfloat16* __restrict__ A1h, const __nv_bfloat16* __restrict__ A1l,
              const uint2* __restrict__ W1h, const uint2* __restrict__ W1l, int K1,
              int NT, const float* __restrict__ bias, int M, int mode,
              const float* __restrict__ f_in, const float* __restrict__ h_in,
              float* __restrict__ out0,
              __nv_bfloat16* __restrict__ outh, __nv_bfloat16* __restrict__ outl) {
    __shared__ __align__(16) __nv_bfloat16 Ash[2][128 * 32];   // 2x8KB hi
    __shared__ __align__(16) __nv_bfloat16 Asl[2][128 * 32];   // 2x8KB lo

    const int tid = threadIdx.x, lane = tid & 31, warp = tid >> 5;
    const int wm = warp & 3, wn = warp >> 2;
    const int m0 = blockIdx.x * 128;
    const int nblk = blockIdx.y;
    const int nt0 = nblk * 16 + wn * 8;
    const uint32_t sbh = smem_to_u32(Ash);
    const uint32_t sbl = smem_to_u32(Asl);

    const int nch0 = K0 >> 5;
    const int nch = nch0 + (A1h ? (K1 >> 5) : 0);

    // per-thread staging slots (2 rows of 16B per buffer)
    const int srow0 = tid >> 2, scu0 = tid & 3;
    const int srow1 = (tid + 256) >> 2, scu1 = (tid + 256) & 3;
    const uint32_t soff0 = srow0 * 64 + ((scu0 ^ ((srow0 >> 1) & 3)) << 4);
    const uint32_t soff1 = srow1 * 64 + ((scu1 ^ ((srow1 >> 1) & 3)) << 4);

    // stage chunk ch into buffer buf
    auto stage = [&](int ch, int buf) {
        const __nv_bfloat16* Ah;
        const __nv_bfloat16* Al;
        int K, kb;
        if (ch < nch0) { Ah = A0h; Al = A0l; K = K0; kb = ch << 5; }
        else           { Ah = A1h; Al = A1l; K = K1; kb = (ch - nch0) << 5; }
        uint32_t bh = sbh + buf * 8192, bl = sbl + buf * 8192;
        int r0 = m0 + srow0, r1 = m0 + srow1;
        int sz0 = (r0 < M) ? 16 : 0, sz1 = (r1 < M) ? 16 : 0;
        if (r0 >= M) r0 = M - 1;
        if (r1 >= M) r1 = M - 1;
        size_t go0 = (size_t)r0 * K + kb + scu0 * 8;
        size_t go1 = (size_t)r1 * K + kb + scu1 * 8;
        cp_async16(bh + soff0, Ah + go0, sz0);
        cp_async16(bh + soff1, Ah + go1, sz1);
        cp_async16(bl + soff0, Al + go0, sz0);
        cp_async16(bl + soff1, Al + go1, sz1);
        cp_commit();
    };

    float c[2][8][4];
#pragma unroll
    for (int i = 0; i < 2; ++i)
#pragma unroll
        for (int j = 0; j < 8; ++j)
#pragma unroll
            for (int k = 0; k < 4; ++k) c[i][j][k] = 0.f;

    const int lr = lane & 7, lmat = lane >> 3;
    const int lrow_off = (lmat & 1) * 8 + lr;
    const int lcu_off = lmat >> 1;

    stage(0, 0);

    for (int ch = 0; ch < nch; ++ch) {
        const int buf = ch & 1;
        cp_wait0();
        __syncthreads();
        if (ch + 1 < nch) stage(ch + 1, buf ^ 1);

        const uint2* Wh;
        const uint2* Wl;
        int gk0;
        if (ch < nch0) { Wh = W0h; Wl = W0l; gk0 = ch * 2; }
        else           { Wh = W1h; Wl = W1l; gk0 = (ch - nch0) * 2; }
        const uint32_t bh32 = sbh + buf * 8192, bl32 = sbl + buf * 8192;

#pragma unroll
        for (int k16 = 0; k16 < 2; ++k16) {
            uint32_t ah[2][4], al[2][4];
#pragma unroll
            for (int mt = 0; mt < 2; ++mt) {
                int row = wm * 32 + mt * 16 + lrow_off;
                int cu = k16 * 2 + lcu_off;
                uint32_t soff = row * 64 + ((cu ^ ((row >> 1) & 3)) << 4);
                asm volatile("ldmatrix.sync.aligned.m8n8.x4.shared.b16 {%0,%1,%2,%3}, [%4];"
                             : "=r"(ah[mt][0]), "=r"(ah[mt][1]), "=r"(ah[mt][2]), "=r"(ah[mt][3])
                             : "r"(bh32 + soff));
                asm volatile("ldmatrix.sync.aligned.m8n8.x4.shared.b16 {%0,%1,%2,%3}, [%4];"
                             : "=r"(al[mt][0]), "=r"(al[mt][1]), "=r"(al[mt][2]), "=r"(al[mt][3])
                             : "r"(bl32 + soff));
            }
            int gk16 = gk0 + k16;
            const uint2* bhp = Wh + ((size_t)gk16 * NT + nt0) * 32 + lane;
            const uint2* blp = Wl + ((size_t)gk16 * NT + nt0) * 32 + lane;
#pragma unroll
            for (int nt = 0; nt < 8; ++nt) {
                uint2 bhv = bhp[nt * 32];
                uint2 blv = blp[nt * 32];
#pragma unroll
                for (int mt = 0; mt < 2; ++mt) {
                    mma16816(c[mt][nt], ah[mt], bhv);
                    mma16816(c[mt][nt], ah[mt], blv);
                    mma16816(c[mt][nt], al[mt], bhv);
                }
            }
        }
    }

    // epilogue
#pragma unroll
    for (int mt = 0; mt < 2; ++mt) {
#pragma unroll
        for (int half = 0; half < 2; ++half) {
            int row = m0 + wm * 32 + mt * 16 + (lane >> 2) + half * 8;
            if (row >= M) continue;
            size_t ro = (size_t)row * HIDC;
#pragma unroll
            for (int nt = 0; nt < 8; ++nt) {
                int col = nblk * 128 + wn * 64 + nt * 8 + (lane & 3) * 2;
                float v0 = c[mt][nt][half * 2 + 0];
                float v1 = c[mt][nt][half * 2 + 1];
                float2 b = *reinterpret_cast<const float2*>(bias + col);
                v0 += b.x; v1 += b.y;
                __nv_bfloat162 hi, lo;
                if (mode == 0) {
                    float o0 = fmaxf(v0, 0.f), o1 = fmaxf(v1, 0.f);
                    *reinterpret_cast<float2*>(out0 + ro + col) = make_float2(o0, o1);
                    split_pair(o0, o1, hi, lo);
                    // zero the padded upper half (cols 128..255); grid.y==1 in mode 0
                    *reinterpret_cast<float2*>(out0 + ro + col + 128) = make_float2(0.f, 0.f);
                    *reinterpret_cast<uint32_t*>(outh + ro + col + 128) = 0u;
                    *reinterpret_cast<uint32_t*>(outl + ro + col + 128) = 0u;
                } else if (mode == 1) {
                    float f0 = 1.f / (1.f + expf(-v0));
                    float f1 = 1.f / (1.f + expf(-v1));
                    float2 h = *reinterpret_cast<const float2*>(h_in + ro + col);
                    *reinterpret_cast<float2*>(out0 + ro + col) = make_float2(f0, f1);
                    split_pair(f0 * h.x, f1 * h.y, hi, lo);
                } else {
                    float t0 = tanhf(v0), t1 = tanhf(v1);
                    float2 f = *reinterpret_cast<const float2*>(f_in + ro + col);
                    float2 h = *reinterpret_cast<const float2*>(h_in + ro + col);
                    float o0 = (1.f - f.x) * h.x + f.x * t0;
                    float o1 = (1.f - f.y) * h.y + f.y * t1;
                    *reinterpret_cast<float2*>(out0 + ro + col) = make_float2(o0, o1);
                    split_pair(o0, o1, hi, lo);
                }
                *reinterpret_cast<__nv_bfloat162*>(outh + ro + col) = hi;
                *reinterpret_cast<__nv_bfloat162*>(outl + ro + col) = lo;
            }
        }
    }
}

// ---------------- readout ----------------
__global__ void colsum_kernel(int nN) {
    int t = threadIdx.x;
    float acc = 0.f;
    for (int r = blockIdx.x; r < nN; r += gridDim.x)
        acc += g_h[(size_t)r * HIDC + t];
    atomicAdd(&g_sum[t], acc);
}
__global__ void final_kernel(const float* __restrict__ Wp, const float* __restrict__ bp,
                             float* __restrict__ out, int nN) {
    __shared__ float sh[HIDC];
    int t = threadIdx.x;
    sh[t] = g_sum[t] * (1.0f / (float)nN) * Wp[t];
    __syncthreads();
    for (int s = 128; s > 0; s >>= 1) {
        if (t < s) sh[t] += sh[t + s];
        __syncthreads();
    }
    if (t == 0) out[0] = sh[0] + bp[0];
}

// ---------------- launch ----------------
extern "C" void kernel_launch(void* const* d_in, const int* in_sizes, int n_in,
                              void* d_out, int out_size) {
    const float* x      = (const float*)d_in[0];
    const int*   ei     = (const int*)d_in[1];   // int32 (jax x64 disabled)
    const float* b_in   = (const float*)d_in[3];
    const float* b_f    = (const float*)d_in[6];
    const float* b_h    = (const float*)d_in[9];
    const float* W_pred = (const float*)d_in[10];
    const float* b_pred = (const float*)d_in[11];
    float* out = (float*)d_out;

    int nN = in_sizes[0] / INFEAT;   // 100000
    int nE = in_sizes[1] / 2;        // 3200000
    const int* srcp = ei;
    const int* dstp = ei + nE;

    void *ph, *pf, *phb, *phl, *pfhb, *pfhl, *pmb, *pml, *pxb, *pxl, *picnt, *psum;
    void *pwih, *pwil, *pwfh, *pwfl, *pufh, *pufl, *pwhh, *pwhl, *puhh, *puhl;
    cudaGetSymbolAddress(&ph, g_h);
    cudaGetSymbolAddress(&pf, g_f);
    cudaGetSymbolAddress(&phb, g_hb);   cudaGetSymbolAddress(&phl, g_hl);
    cudaGetSymbolAddress(&pfhb, g_fhb); cudaGetSymbolAddress(&pfhl, g_fhl);
    cudaGetSymbolAddress(&pmb, g_mb);   cudaGetSymbolAddress(&pml, g_ml);
    cudaGetSymbolAddress(&pxb, g_xb);   cudaGetSymbolAddress(&pxl, g_xl);
    cudaGetSymbolAddress(&picnt, g_icnt);
    cudaGetSymbolAddress(&psum, g_sum);
    cudaGetSymbolAddress(&pwih, g_wih); cudaGetSymbolAddress(&pwil, g_wil);
    cudaGetSymbolAddress(&pwfh, g_wfh); cudaGetSymbolAddress(&pwfl, g_wfl);
    cudaGetSymbolAddress(&pufh, g_ufh); cudaGetSymbolAddress(&pufl, g_ufl);
    cudaGetSymbolAddress(&pwhh, g_whh); cudaGetSymbolAddress(&pwhl, g_whl);
    cudaGetSymbolAddress(&puhh, g_uhh); cudaGetSymbolAddress(&puhl, g_uhl);
    float* hbuf = (float*)ph;
    float* fbuf = (float*)pf;
    __nv_bfloat16 *hb = (__nv_bfloat16*)phb,  *hl = (__nv_bfloat16*)phl;
    __nv_bfloat16 *fhb = (__nv_bfloat16*)pfhb, *fhl = (__nv_bfloat16*)pfhl;
    __nv_bfloat16 *mb = (__nv_bfloat16*)pmb,  *ml = (__nv_bfloat16*)pml;

    // launch order tuned so ncu (-s 5 -c 1) captures the encode gemm_mma:
    // 1 memset(icnt), 2 count, 3 scan, 4 fill, 5 prep, 6 gemm_mma(encode)
    cudaMemsetAsync(picnt, 0, (size_t)nN * sizeof(int));
    count_kernel<<<(nE + 255) / 256, 256>>>(dstp, nE);
    scan_kernel<<<1, 1024>>>(nN);
    fill_kernel<<<(nE + 255) / 256, 256>>>(srcp, dstp, nE);

    int prep_threads = 4096 + 4 * 16384 + nN * INFEAT / 2;
    prep_kernel<<<(prep_threads + 255) / 256, 256>>>(
        x, (const float*)d_in[2], (const float*)d_in[4], (const float*)d_in[5],
        (const float*)d_in[7], (const float*)d_in[8], nN * INFEAT);

    int gmx = (nN + 127) / 128;
    // encode: h = relu(x @ W_in^T + b_in); epilogue zero-fills cols 128..255
    gemm_mma<<<dim3(gmx, 1), 256>>>(
        (__nv_bfloat16*)pxb, (__nv_bfloat16*)pxl, (uint2*)pwih, (uint2*)pwil, INFEAT,
        nullptr, nullptr, nullptr, nullptr, 0, 16,
        b_in, nN, 0, nullptr, nullptr, hbuf, hb, hl);

    int gather_blocks = (nN + 7) / 8;
    for (int step = 0; step < 4; ++step) {
        gather_kernel<<<gather_blocks, 256>>>(nN);
        gemm_mma<<<dim3(gmx, 2), 256>>>(
            mb, ml, (uint2*)pwfh, (uint2*)pwfl, HIDC,
            hb, hl, (uint2*)pufh, (uint2*)pufl, HIDC, 32,
            b_f, nN, 1, nullptr, hbuf, fbuf, fhb, fhl);
        gemm_mma<<<dim3(gmx, 2), 256>>>(
            mb, ml, (uint2*)pwhh, (uint2*)pwhl, HIDC,
            fhb, fhl, (uint2*)puhh, (uint2*)puhl, HIDC, 32,
            b_h, nN, 2, fbuf, hbuf, hbuf, hb, hl);
    }

    cudaMemsetAsync(psum, 0, HIDC * sizeof(float));
    colsum_kernel<<<1024, 256>>>(nN);
    final_kernel<<<1, 256>>>(W_pred, b_pred, out, nN);
}

// round 12
// speedup vs baseline: 1.1283x; 1.1283x over previous
#include <cuda_runtime.h>
#include <cuda_bf16.h>
#include <cstdint>
#include <math.h>

#define NN_MAX 100000
#define NE_MAX 3200000
#define HIDC   256
#define INFEAT 128

// ---------------- scratch (static __device__ globals; no allocation) ----------
__device__ float g_h  [(size_t)NN_MAX * HIDC];
__device__ float g_f  [(size_t)NN_MAX * HIDC];
__device__ __nv_bfloat16 g_hb [(size_t)NN_MAX * HIDC], g_hl [(size_t)NN_MAX * HIDC];
__device__ __nv_bfloat16 g_fhb[(size_t)NN_MAX * HIDC], g_fhl[(size_t)NN_MAX * HIDC];
__device__ __nv_bfloat16 g_mb [(size_t)NN_MAX * HIDC], g_ml [(size_t)NN_MAX * HIDC];
__device__ __nv_bfloat16 g_xb [(size_t)NN_MAX * INFEAT], g_xl [(size_t)NN_MAX * INFEAT];
// fragment-ordered weights: [K/16][N/8][32 lanes][2 regs] as uint2 per lane
__device__ uint2 g_wih[4096],  g_wil[4096];
__device__ uint2 g_wfh[16384], g_wfl[16384];
__device__ uint2 g_ufh[16384], g_ufl[16384];
__device__ uint2 g_whh[16384], g_whl[16384];
__device__ uint2 g_uhh[16384], g_uhl[16384];
// CSR (grouped by destination); g_icnt zero-initialized at module load,
// re-zeroed by zero_icnt at the end of each launch (graph replays stay clean)
__device__ int g_icnt[NN_MAX];
__device__ int g_off [NN_MAX + 1];
__device__ int g_pos [NN_MAX];
__device__ int g_csrc[NE_MAX];
__device__ float g_sum[HIDC];

__device__ __forceinline__ uint32_t smem_to_u32(const void* p) {
    uint32_t a;
    asm("{ .reg .u64 t; cvta.to.shared.u64 t, %1; cvt.u32.u64 %0, t; }" : "=r"(a) : "l"(p));
    return a;
}

__device__ __forceinline__ void split_pair(float a, float b,
                                           __nv_bfloat162& hi, __nv_bfloat162& lo) {
    __nv_bfloat16 h0 = __float2bfloat16_rn(a);
    __nv_bfloat16 h1 = __float2bfloat16_rn(b);
    hi = __nv_bfloat162(h0, h1);
    lo = __nv_bfloat162(__float2bfloat16_rn(a - __bfloat162float(h0)),
                        __float2bfloat16_rn(b - __bfloat162float(h1)));
}

// ---------------- CSR build ----------------
__global__ void count_kernel(const int* __restrict__ dst, int nE) {
    int i = blockIdx.x * blockDim.x + threadIdx.x;
    if (i < nE) atomicAdd(&g_icnt[dst[i]], 1);
}

__global__ void scan_kernel(int nN) {
    __shared__ int part[1024];
    int t = threadIdx.x;
    int chunk = (nN + 1023) / 1024;
    int b = t * chunk;
    int e = min(b + chunk, nN);
    int s = 0;
    for (int i = b; i < e; ++i) s += g_icnt[i];
    part[t] = s;
    __syncthreads();
    for (int d = 1; d < 1024; d <<= 1) {
        int v = (t >= d) ? part[t - d] : 0;
        __syncthreads();
        part[t] += v;
        __syncthreads();
    }
    int run = part[t] - s;
    for (int i = b; i < e; ++i) {
        g_off[i] = run;
        g_pos[i] = run;
        run += g_icnt[i];
    }
    if (t == 1023) g_off[nN] = part[1023];
}

__global__ void fill_kernel(const int* __restrict__ src,
                            const int* __restrict__ dst, int nE) {
    int i = blockIdx.x * blockDim.x + threadIdx.x;
    if (i < nE) {
        int p = atomicAdd(&g_pos[dst[i]], 1);
        g_csrc[p] = src[i];
    }
}

__global__ void zero_icnt(int nN) {
    int i = blockIdx.x * blockDim.x + threadIdx.x;
    if (i < nN) g_icnt[i] = 0;
}

// ---------------- pull-mode aggregation: one warp per destination node -------
__global__ __launch_bounds__(256)
void gather_kernel(int nN) {
    int w = (blockIdx.x * blockDim.x + threadIdx.x) >> 5;
    int lane = threadIdx.x & 31;
    if (w >= nN) return;
    int beg = g_off[w], end = g_off[w + 1];
    float acc[8] = {0.f, 0.f, 0.f, 0.f, 0.f, 0.f, 0.f, 0.f};
    int e = beg;
    for (; e + 1 < end; e += 2) {
        int s0 = g_csrc[e];
        int s1 = g_csrc[e + 1];
        const float4* r0 = reinterpret_cast<const float4*>(g_h + (size_t)s0 * HIDC) + lane * 2;
        const float4* r1 = reinterpret_cast<const float4*>(g_h + (size_t)s1 * HIDC) + lane * 2;
        float4 a0 = r0[0], a1 = r0[1];
        float4 b0 = r1[0], b1 = r1[1];
        acc[0] += a0.x + b0.x; acc[1] += a0.y + b0.y;
        acc[2] += a0.z + b0.z; acc[3] += a0.w + b0.w;
        acc[4] += a1.x + b1.x; acc[5] += a1.y + b1.y;
        acc[6] += a1.z + b1.z; acc[7] += a1.w + b1.w;
    }
    if (e < end) {
        int s0 = g_csrc[e];
        const float4* r0 = reinterpret_cast<const float4*>(g_h + (size_t)s0 * HIDC) + lane * 2;
        float4 a0 = r0[0], a1 = r0[1];
        acc[0] += a0.x; acc[1] += a0.y; acc[2] += a0.z; acc[3] += a0.w;
        acc[4] += a1.x; acc[5] += a1.y; acc[6] += a1.z; acc[7] += a1.w;
    }
    float inv = 1.f / fmaxf((float)(end - beg), 1.f);
    __nv_bfloat162 hi[4], lo[4];
    split_pair(acc[0] * inv, acc[1] * inv, hi[0], lo[0]);
    split_pair(acc[2] * inv, acc[3] * inv, hi[1], lo[1]);
    split_pair(acc[4] * inv, acc[5] * inv, hi[2], lo[2]);
    split_pair(acc[6] * inv, acc[7] * inv, hi[3], lo[3]);
    size_t o = (size_t)w * HIDC + lane * 8;
    *reinterpret_cast<uint4*>(g_mb + o) = *reinterpret_cast<const uint4*>(hi);
    *reinterpret_cast<uint4*>(g_ml + o) = *reinterpret_cast<const uint4*>(lo);
}

// ---------------- consolidated prep: 5 weight-frag sections + x split --------
__device__ void wfrag_one(const float* W, uint2* hi, uint2* lo, int N, int K, int i) {
    int lane = i & 31;
    int rest = i >> 5;
    int n8 = rest % (N / 8);
    int k16 = rest / (N / 8);
    int n = n8 * 8 + (lane >> 2);
    uint32_t rh[2], rl[2];
#pragma unroll
    for (int reg = 0; reg < 2; ++reg) {
        int k = k16 * 16 + reg * 8 + (lane & 3) * 2;
        float w0 = W[(size_t)n * K + k];
        float w1 = W[(size_t)n * K + k + 1];
        __nv_bfloat16 h0 = __float2bfloat16_rn(w0);
        __nv_bfloat16 h1 = __float2bfloat16_rn(w1);
        rh[reg] = ((uint32_t)__bfloat16_as_ushort(h1) << 16) | __bfloat16_as_ushort(h0);
        rl[reg] = ((uint32_t)__bfloat16_as_ushort(__float2bfloat16_rn(w1 - __bfloat162float(h1))) << 16)
                | __bfloat16_as_ushort(__float2bfloat16_rn(w0 - __bfloat162float(h0)));
    }
    hi[i] = make_uint2(rh[0], rh[1]);
    lo[i] = make_uint2(rl[0], rl[1]);
}

__global__ void prep_kernel(const float* __restrict__ x,
                            const float* __restrict__ Win, const float* __restrict__ Wf,
                            const float* __restrict__ Uf, const float* __restrict__ Wh,
                            const float* __restrict__ Uh, int nx) {
    int i = blockIdx.x * blockDim.x + threadIdx.x;
    if (i < 4096) { wfrag_one(Win, g_wih, g_wil, 128, 128, i); return; }
    i -= 4096;
    if (i < 16384) { wfrag_one(Wf, g_wfh, g_wfl, 256, 256, i); return; }
    i -= 16384;
    if (i < 16384) { wfrag_one(Uf, g_ufh, g_ufl, 256, 256, i); return; }
    i -= 16384;
    if (i < 16384) { wfrag_one(Wh, g_whh, g_whl, 256, 256, i); return; }
    i -= 16384;
    if (i < 16384) { wfrag_one(Uh, g_uhh, g_uhl, 256, 256, i); return; }
    i -= 16384;
    int j = i * 2;
    if (j < nx) {
        __nv_bfloat162 hi, lo;
        split_pair(x[j], x[j + 1], hi, lo);
        *reinterpret_cast<__nv_bfloat162*>(g_xb + j) = hi;
        *reinterpret_cast<__nv_bfloat162*>(g_xl + j) = lo;
    }
}

// ---------------- HMMA dual-GEMM, register-staged A prefetch ------------------
// C = sum_pass [ Ah*(Wh+Wl) + Al*Wh ]
__device__ __forceinline__ void mma16816(float c[4], const uint32_t a[4], uint2 b) {
    asm volatile("mma.sync.aligned.m16n8k16.row.col.f32.bf16.bf16.f32 "
                 "{%0,%1,%2,%3}, {%4,%5,%6,%7}, {%8,%9}, {%0,%1,%2,%3};"
                 : "+f"(c[0]), "+f"(c[1]), "+f"(c[2]), "+f"(c[3])
                 : "r"(a[0]), "r"(a[1]), "r"(a[2]), "r"(a[3]), "r"(b.x), "r"(b.y));
}

__global__ __launch_bounds__(256)
void gemm_mma(const __nv_bfloat16* __restrict__ A0h, const __nv_bfloat16* __restrict__ A0l,
              const uint2* __restrict__ W0h, const uint2* __restrict__ W0l, int K0,
              const __nv_bfloat16* __restrict__ A1h, const __nv_bfloat16* __restrict__ A1l,
              const uint2* __restrict__ W1h, const uint2* __restrict__ W1l, int K1,
              int NT, const float* __restrict__ bias, int M, int mode,
              const float* __restrict__ f_in, const float* __restrict__ h_in,
              float* __restrict__ out0,
              __nv_bfloat16* __restrict__ outh, __nv_bfloat16* __restrict__ outl) {
    __shared__ __align__(16) __nv_bfloat16 Ash[128 * 32];   // 8KB hi
    __shared__ __align__(16) __nv_bfloat16 Asl[128 * 32];   // 8KB lo

    const int tid = threadIdx.x, lane = tid & 31, warp = tid >> 5;
    const int wm = warp & 3, wn = warp >> 2;
    const int m0 = blockIdx.x * 128;
    const int nblk = blockIdx.y;
    const int nt0 = nblk * 16 + wn * 8;
    const uint32_t sbh = smem_to_u32(Ash);
    const uint32_t sbl = smem_to_u32(Asl);

    const int nch0 = K0 >> 5;
    const int nch = nch0 + (A1h ? (K1 >> 5) : 0);

    // per-thread staging slots (2 rows of 16B each, hi+lo)
    const int srow0 = tid >> 2, scu0 = tid & 3;
    const int srow1 = (tid + 256) >> 2, scu1 = (tid + 256) & 3;
    const uint32_t soff0 = srow0 * 64 + ((scu0 ^ ((srow0 >> 1) & 3)) << 4);
    const uint32_t soff1 = srow1 * 64 + ((scu1 ^ ((srow1 >> 1) & 3)) << 4);

    uint4 rh0, rh1, rl0, rl1;   // register-staged next A chunk

    auto loadregs = [&](int ch) {
        const __nv_bfloat16 *Ah, *Al;
        int K, kb;
        if (ch < nch0) { Ah = A0h; Al = A0l; K = K0; kb = ch << 5; }
        else           { Ah = A1h; Al = A1l; K = K1; kb = (ch - nch0) << 5; }
        rh0 = make_uint4(0, 0, 0, 0); rl0 = rh0; rh1 = rh0; rl1 = rh0;
        int r0 = m0 + srow0, r1 = m0 + srow1;
        if (r0 < M) {
            size_t go = (size_t)r0 * K + kb + scu0 * 8;
            rh0 = *reinterpret_cast<const uint4*>(Ah + go);
            rl0 = *reinterpret_cast<const uint4*>(Al + go);
        }
        if (r1 < M) {
            size_t go = (size_t)r1 * K + kb + scu1 * 8;
            rh1 = *reinterpret_cast<const uint4*>(Ah + go);
            rl1 = *reinterpret_cast<const uint4*>(Al + go);
        }
    };

    float c[2][8][4];
#pragma unroll
    for (int i = 0; i < 2; ++i)
#pragma unroll
        for (int j = 0; j < 8; ++j)
#pragma unroll
            for (int k = 0; k < 4; ++k) c[i][j][k] = 0.f;

    const int lr = lane & 7, lmat = lane >> 3;
    const int lrow_off = (lmat & 1) * 8 + lr;
    const int lcu_off = lmat >> 1;

    loadregs(0);

    for (int ch = 0; ch < nch; ++ch) {
        __syncthreads();   // consumers of previous chunk done with smem
        *reinterpret_cast<uint4*>(reinterpret_cast<char*>(Ash) + soff0) = rh0;
        *reinterpret_cast<uint4*>(reinterpret_cast<char*>(Ash) + soff1) = rh1;
        *reinterpret_cast<uint4*>(reinterpret_cast<char*>(Asl) + soff0) = rl0;
        *reinterpret_cast<uint4*>(reinterpret_cast<char*>(Asl) + soff1) = rl1;
        __syncthreads();
        if (ch + 1 < nch) loadregs(ch + 1);   // global latency hides under MMA

        const uint2* Wh;
        const uint2* Wl;
        int gk0;
        if (ch < nch0) { Wh = W0h; Wl = W0l; gk0 = ch * 2; }
        else           { Wh = W1h; Wl = W1l; gk0 = (ch - nch0) * 2; }

#pragma unroll
        for (int k16 = 0; k16 < 2; ++k16) {
            uint32_t ah[2][4], al[2][4];
#pragma unroll
            for (int mt = 0; mt < 2; ++mt) {
                int row = wm * 32 + mt * 16 + lrow_off;
                int cu = k16 * 2 + lcu_off;
                uint32_t soff = row * 64 + ((cu ^ ((row >> 1) & 3)) << 4);
                asm volatile("ldmatrix.sync.aligned.m8n8.x4.shared.b16 {%0,%1,%2,%3}, [%4];"
                             : "=r"(ah[mt][0]), "=r"(ah[mt][1]), "=r"(ah[mt][2]), "=r"(ah[mt][3])
                             : "r"(sbh + soff));
                asm volatile("ldmatrix.sync.aligned.m8n8.x4.shared.b16 {%0,%1,%2,%3}, [%4];"
                             : "=r"(al[mt][0]), "=r"(al[mt][1]), "=r"(al[mt][2]), "=r"(al[mt][3])
                             : "r"(sbl + soff));
            }
            int gk16 = gk0 + k16;
            const uint2* bhp = Wh + ((size_t)gk16 * NT + nt0) * 32 + lane;
            const uint2* blp = Wl + ((size_t)gk16 * NT + nt0) * 32 + lane;
#pragma unroll
            for (int nt = 0; nt < 8; ++nt) {
                uint2 bhv = bhp[nt * 32];
                uint2 blv = blp[nt * 32];
#pragma unroll
                for (int mt = 0; mt < 2; ++mt) {
                    mma16816(c[mt][nt], ah[mt], bhv);
                    mma16816(c[mt][nt], ah[mt], blv);
                    mma16816(c[mt][nt], al[mt], bhv);
                }
            }
        }
    }

    // epilogue
#pragma unroll
    for (int mt = 0; mt < 2; ++mt) {
#pragma unroll
        for (int half = 0; half < 2; ++half) {
            int row = m0 + wm * 32 + mt * 16 + (lane >> 2) + half * 8;
            if (row >= M) continue;
            size_t ro = (size_t)row * HIDC;
#pragma unroll
            for (int nt = 0; nt < 8; ++nt) {
                int col = nblk * 128 + wn * 64 + nt * 8 + (lane & 3) * 2;
                float v0 = c[mt][nt][half * 2 + 0];
                float v1 = c[mt][nt][half * 2 + 1];
                float2 b = *reinterpret_cast<const float2*>(bias + col);
                v0 += b.x; v1 += b.y;
                __nv_bfloat162 hi, lo;
                if (mode == 0) {
                    float o0 = fmaxf(v0, 0.f), o1 = fmaxf(v1, 0.f);
                    *reinterpret_cast<float2*>(out0 + ro + col) = make_float2(o0, o1);
                    split_pair(o0, o1, hi, lo);
                    // zero the padded upper half (cols 128..255); grid.y==1 in mode 0
                    *reinterpret_cast<float2*>(out0 + ro + col + 128) = make_float2(0.f, 0.f);
                    *reinterpret_cast<uint32_t*>(outh + ro + col + 128) = 0u;
                    *reinterpret_cast<uint32_t*>(outl + ro + col + 128) = 0u;
                } else if (mode == 1) {
                    float f0 = 1.f / (1.f + expf(-v0));
                    float f1 = 1.f / (1.f + expf(-v1));
                    float2 h = *reinterpret_cast<const float2*>(h_in + ro + col);
                    *reinterpret_cast<float2*>(out0 + ro + col) = make_float2(f0, f1);
                    split_pair(f0 * h.x, f1 * h.y, hi, lo);
                } else {
                    float t0 = tanhf(v0), t1 = tanhf(v1);
                    float2 f = *reinterpret_cast<const float2*>(f_in + ro + col);
                    float2 h = *reinterpret_cast<const float2*>(h_in + ro + col);
                    float o0 = (1.f - f.x) * h.x + f.x * t0;
                    float o1 = (1.f - f.y) * h.y + f.y * t1;
                    *reinterpret_cast<float2*>(out0 + ro + col) = make_float2(o0, o1);
                    split_pair(o0, o1, hi, lo);
                }
                *reinterpret_cast<__nv_bfloat162*>(outh + ro + col) = hi;
                *reinterpret_cast<__nv_bfloat162*>(outl + ro + col) = lo;
            }
        }
    }
}

// ---------------- readout ----------------
__global__ void colsum_kernel(int nN) {
    int t = threadIdx.x;
    float acc = 0.f;
    for (int r = blockIdx.x; r < nN; r += gridDim.x)
        acc += g_h[(size_t)r * HIDC + t];
    atomicAdd(&g_sum[t], acc);
}
__global__ void final_kernel(const float* __restrict__ Wp, const float* __restrict__ bp,
                             float* __restrict__ out, int nN) {
    __shared__ float sh[HIDC];
    int t = threadIdx.x;
    sh[t] = g_sum[t] * (1.0f / (float)nN) * Wp[t];
    __syncthreads();
    for (int s = 128; s > 0; s >>= 1) {
        if (t < s) sh[t] += sh[t + s];
        __syncthreads();
    }
    if (t == 0) out[0] = sh[0] + bp[0];
}

// ---------------- launch ----------------
extern "C" void kernel_launch(void* const* d_in, const int* in_sizes, int n_in,
                              void* d_out, int out_size) {
    const float* x      = (const float*)d_in[0];
    const int*   ei     = (const int*)d_in[1];   // int32 (jax x64 disabled)
    const float* b_in   = (const float*)d_in[3];
    const float* b_f    = (const float*)d_in[6];
    const float* b_h    = (const float*)d_in[9];
    const float* W_pred = (const float*)d_in[10];
    const float* b_pred = (const float*)d_in[11];
    float* out = (float*)d_out;

    int nN = in_sizes[0] / INFEAT;   // 100000
    int nE = in_sizes[1] / 2;        // 3200000
    const int* srcp = ei;
    const int* dstp = ei + nE;

    void *ph, *pf, *phb, *phl, *pfhb, *pfhl, *pmb, *pml, *pxb, *pxl, *psum;
    void *pwih, *pwil, *pwfh, *pwfl, *pufh, *pufl, *pwhh, *pwhl, *puhh, *puhl;
    cudaGetSymbolAddress(&ph, g_h);
    cudaGetSymbolAddress(&pf, g_f);
    cudaGetSymbolAddress(&phb, g_hb);   cudaGetSymbolAddress(&phl, g_hl);
    cudaGetSymbolAddress(&pfhb, g_fhb); cudaGetSymbolAddress(&pfhl, g_fhl);
    cudaGetSymbolAddress(&pmb, g_mb);   cudaGetSymbolAddress(&pml, g_ml);
    cudaGetSymbolAddress(&pxb, g_xb);   cudaGetSymbolAddress(&pxl, g_xl);
    cudaGetSymbolAddress(&psum, g_sum);
    cudaGetSymbolAddress(&pwih, g_wih); cudaGetSymbolAddress(&pwil, g_wil);
    cudaGetSymbolAddress(&pwfh, g_wfh); cudaGetSymbolAddress(&pwfl, g_wfl);
    cudaGetSymbolAddress(&pufh, g_ufh); cudaGetSymbolAddress(&pufl, g_ufl);
    cudaGetSymbolAddress(&pwhh, g_whh); cudaGetSymbolAddress(&pwhl, g_whl);
    cudaGetSymbolAddress(&puhh, g_uhh); cudaGetSymbolAddress(&puhl, g_uhl);
    float* hbuf = (float*)ph;
    float* fbuf = (float*)pf;
    __nv_bfloat16 *hb = (__nv_bfloat16*)phb,  *hl = (__nv_bfloat16*)phl;
    __nv_bfloat16 *fhb = (__nv_bfloat16*)pfhb, *fhl = (__nv_bfloat16*)pfhl;
    __nv_bfloat16 *mb = (__nv_bfloat16*)pmb,  *ml = (__nv_bfloat16*)pml;

    // g_icnt is zero at first call (module-load zero-init) and re-zeroed by
    // zero_icnt at the end of every launch, so graph replays stay deterministic.
    count_kernel<<<(nE + 255) / 256, 256>>>(dstp, nE);
    scan_kernel<<<1, 1024>>>(nN);
    fill_kernel<<<(nE + 255) / 256, 256>>>(srcp, dstp, nE);

    int prep_threads = 4096 + 4 * 16384 + nN * INFEAT / 2;
    prep_kernel<<<(prep_threads + 255) / 256, 256>>>(
        x, (const float*)d_in[2], (const float*)d_in[4], (const float*)d_in[5],
        (const float*)d_in[7], (const float*)d_in[8], nN * INFEAT);

    int gmx = (nN + 127) / 128;
    // encode: h = relu(x @ W_in^T + b_in); epilogue zero-fills cols 128..255
    gemm_mma<<<dim3(gmx, 1), 256>>>(
        (__nv_bfloat16*)pxb, (__nv_bfloat16*)pxl, (uint2*)pwih, (uint2*)pwil, INFEAT,
        nullptr, nullptr, nullptr, nullptr, 0, 16,
        b_in, nN, 0, nullptr, nullptr, hbuf, hb, hl);

    int gather_blocks = (nN + 7) / 8;
    for (int step = 0; step < 4; ++step) {
        gather_kernel<<<gather_blocks, 256>>>(nN);
        gemm_mma<<<dim3(gmx, 2), 256>>>(
            mb, ml, (uint2*)pwfh, (uint2*)pwfl, HIDC,
            hb, hl, (uint2*)pufh, (uint2*)pufl, HIDC, 32,
            b_f, nN, 1, nullptr, hbuf, fbuf, fhb, fhl);
        gemm_mma<<<dim3(gmx, 2), 256>>>(
            mb, ml, (uint2*)pwhh, (uint2*)pwhl, HIDC,
            fhb, fhl, (uint2*)puhh, (uint2*)puhl, HIDC, 32,
            b_h, nN, 2, fbuf, hbuf, hbuf, hb, hl);
    }

    cudaMemsetAsync(psum, 0, HIDC * sizeof(float));
    colsum_kernel<<<1024, 256>>>(nN);
    final_kernel<<<1, 256>>>(W_pred, b_pred, out, nN);
    zero_icnt<<<(nN + 255) / 256, 256>>>(nN);   // reset for next replay
}